// round 5
// baseline (speedup 1.0000x reference)
#include <cuda_runtime.h>
#include <math.h>
#include <float.h>

// Problem constants (shapes fixed by setup_inputs)
#define D_DIM  640
#define D4     160         // D_DIM / 4
#define S_SHOT 5
#define W_WAY  5
#define TOPK   8
#define M_MAX  50000
#define NS_MAX (M_MAX + S_SHOT)

#define SIM_BLOCKS  592    // 4 blocks/SM * 148
#define SIM_THREADS 256
#define SIM_WARPS   (SIM_THREADS / 32)

#define PT_SLICES   64     // partial top-k blocks per way
#define PT_THREADS  256
#define NCAND       (PT_SLICES * TOPK)

// Static device scratch (no allocations allowed)
__device__ float g_sim[W_WAY][NS_MAX];     // sim[w][m]; slots 0..4 unused here
__device__ float g_candv[W_WAY][NCAND];
__device__ int   g_candi[W_WAY][NCAND];

__device__ __forceinline__ float dot4(float4 a, float4 b) {
    return a.x * b.x + a.y * b.y + a.z * b.z + a.w * b.w;
}

// ---------------------------------------------------------------------------
// Sorted-8 (desc) register list helpers.
// Strictly-greater compare => earlier-seen (lower index) wins on ties.
// ---------------------------------------------------------------------------
#define INS(J) do {                                        \
    _Pragma("unroll")                                      \
    for (int kk = TOPK - 1; kk > (J); --kk) {              \
        av[kk] = av[kk - 1]; ai[kk] = ai[kk - 1];          \
    }                                                      \
    av[J] = x; ai[J] = i;                                  \
} while (0)

#define FILTER_INSERT() do {                                            \
    if (x > av[7]) {                                                    \
        if (x > av[3]) {                                                \
            if (x > av[1]) { if (x > av[0]) INS(0); else INS(1); }      \
            else           { if (x > av[2]) INS(2); else INS(3); }      \
        } else {                                                        \
            if (x > av[5]) { if (x > av[4]) INS(4); else INS(5); }      \
            else           { if (x > av[6]) INS(6); else INS(7); }      \
        }                                                               \
    }                                                                   \
} while (0)

__device__ __forceinline__ bool better(float x, int i, float y, int j) {
    return (x > y) || (x == y && i < j);
}

// Shared-memory tree merge of NT sorted-8 lists (desc, index-asc ties).
template <int NT>
__device__ __forceinline__ void tree_merge8(float* sv, int* si, int tid) {
    for (int stride = NT >> 1; stride >= 1; stride >>= 1) {
        __syncthreads();
        if (tid < stride) {
            float la[TOPK], lb[TOPK], ov[TOPK];
            int   lia[TOPK], lib[TOPK], oi[TOPK];
            #pragma unroll
            for (int k = 0; k < TOPK; ++k) {
                la[k]  = sv[tid * TOPK + k];            lia[k] = si[tid * TOPK + k];
                lb[k]  = sv[(tid + stride) * TOPK + k]; lib[k] = si[(tid + stride) * TOPK + k];
            }
            int pa = 0, pb = 0;
            #pragma unroll
            for (int k = 0; k < TOPK; ++k) {
                bool takeA = (la[pa] > lb[pb]) ||
                             (la[pa] == lb[pb] && lia[pa] <= lib[pb]);
                if (takeA) { ov[k] = la[pa]; oi[k] = lia[pa]; ++pa; }
                else       { ov[k] = lb[pb]; oi[k] = lib[pb]; ++pb; }
            }
            #pragma unroll
            for (int k = 0; k < TOPK; ++k) { sv[tid * TOPK + k] = ov[k]; si[tid * TOPK + k] = oi[k]; }
        }
    }
    __syncthreads();
}

// ---------------------------------------------------------------------------
// Kernel 1: the 128 MB streaming pass.
// Quarter-warp per row: lane 8q+s handles row base+q, reading float4s s+8j.
// LDG stays fully coalesced (4 consecutive 128B sectors per instruction),
// s_q LDS is a 4-way broadcast, and the reduction is only 3 butterfly steps
// over 6 accumulators (18 SHFL per 4 rows vs 120 in the old 32-lane scheme).
// ---------------------------------------------------------------------------
__global__ void __launch_bounds__(SIM_THREADS, 4)
sim_kernel(const float* __restrict__ sup, const float* __restrict__ mem, int M) {
    __shared__ float  s_inv[S_SHOT * W_WAY];
    __shared__ float4 s_q[W_WAY * D4];        // 12.8 KB

    int tid = threadIdx.x, wid = tid >> 5, lane = tid & 31;
    const float4* sup4 = reinterpret_cast<const float4*>(sup);

    // prep phase 1: inverse norms of the 25 support vectors
    for (int v = wid; v < S_SHOT * W_WAY; v += SIM_WARPS) {
        const float4* p = sup4 + v * D4;
        float ss = 0.f;
        #pragma unroll
        for (int j = 0; j < 5; ++j) { float4 x = p[lane + j * 32]; ss += dot4(x, x); }
        #pragma unroll
        for (int o = 16; o; o >>= 1) ss += __shfl_xor_sync(0xffffffffu, ss, o);
        if (lane == 0) s_inv[v] = 1.0f / fmaxf(sqrtf(ss), 1e-12f);
    }
    __syncthreads();

    // prep phase 2: q[w] (includes the 1/S mean factor)
    for (int i = tid; i < W_WAY * D4; i += SIM_THREADS) {
        int w = i / D4, d = i - w * D4;
        float4 acc = make_float4(0.f, 0.f, 0.f, 0.f);
        #pragma unroll
        for (int s = 0; s < S_SHOT; ++s) {
            float4 x = sup4[(s * W_WAY + w) * D4 + d];
            float iv = s_inv[s * W_WAY + w] * (1.0f / (float)S_SHOT);
            acc.x += x.x * iv; acc.y += x.y * iv; acc.z += x.z * iv; acc.w += x.w * iv;
        }
        s_q[i] = acc;
    }
    __syncthreads();

    // mainloop: balanced contiguous partition of row-quads across all warps
    int quads = (M + 3) >> 2;
    int gw = blockIdx.x * SIM_WARPS + wid;
    int nw = SIM_BLOCKS * SIM_WARPS;
    int qb = (int)(((long long)gw * quads) / nw);
    int qe = (int)(((long long)(gw + 1) * quads) / nw);

    int q = lane >> 3;          // row within quad (0..3)
    int s = lane & 7;           // sub-position within row (0..7)
    const float4* base = reinterpret_cast<const float4*>(mem);

    for (int g = qb; g < qe; ++g) {
        int row = (g << 2) + q;
        int rowc = min(row, M - 1);          // clamp (no tail at M=50000)
        const float4* r = base + (size_t)rowc * D4 + s;

        float ss = 0.f;
        float dp[W_WAY] = {0.f, 0.f, 0.f, 0.f, 0.f};

        #pragma unroll
        for (int j = 0; j < 20; ++j) {
            float4 v = r[j * 8];
            ss += dot4(v, v);
            #pragma unroll
            for (int w = 0; w < W_WAY; ++w)
                dp[w] += dot4(v, s_q[w * D4 + s + j * 8]);
        }

        // reduce over the 8 lanes of this quarter-warp (3 butterfly steps)
        #pragma unroll
        for (int o = 4; o; o >>= 1) {
            ss += __shfl_xor_sync(0xffffffffu, ss, o);
            #pragma unroll
            for (int w = 0; w < W_WAY; ++w)
                dp[w] += __shfl_xor_sync(0xffffffffu, dp[w], o);
        }

        if (s == 0 && row < M) {
            float inv = 1.0f / fmaxf(sqrtf(ss), 1e-12f);
            #pragma unroll
            for (int w = 0; w < W_WAY; ++w)
                g_sim[w][S_SHOT + row] = dp[w] * inv;
        }
    }
}

// ---------------------------------------------------------------------------
// Kernel 2: parallel partial top-k. Grid (PT_SLICES, W_WAY). Each block scans
// a contiguous slice of g_sim[w] (L2-hot), produces its top-8 candidates.
// ---------------------------------------------------------------------------
__global__ void __launch_bounds__(PT_THREADS)
partial_topk(int M) {
    __shared__ float sv[PT_THREADS * TOPK];
    __shared__ int   si[PT_THREADS * TOPK];
    int w = blockIdx.y;
    int slice = blockIdx.x;
    int tid = threadIdx.x;

    int beg = (int)(((long long)slice * M) / PT_SLICES);
    int end = (int)(((long long)(slice + 1) * M) / PT_SLICES);

    float av[TOPK]; int ai[TOPK];
    #pragma unroll
    for (int k = 0; k < TOPK; ++k) { av[k] = -FLT_MAX; ai[k] = 0x7fffffff; }

    for (int m = beg + tid; m < end; m += PT_THREADS) {
        int i = S_SHOT + m;
        float x = g_sim[w][i];
        FILTER_INSERT();
    }

    #pragma unroll
    for (int k = 0; k < TOPK; ++k) { sv[tid * TOPK + k] = av[k]; si[tid * TOPK + k] = ai[k]; }
    tree_merge8<PT_THREADS>(sv, si, tid);

    if (tid < TOPK) {
        g_candv[w][slice * TOPK + tid] = sv[tid];
        g_candi[w][slice * TOPK + tid] = si[tid];
    }
}

// ---------------------------------------------------------------------------
// Kernel 3: per-way final merge + gather. Recomputes the 5 support self-sims
// locally (tiny, L2-hot), merges the 512 candidates + support, gathers rows.
// ---------------------------------------------------------------------------
#define FT_THREADS 256

__global__ void __launch_bounds__(FT_THREADS)
final_kernel(const float* __restrict__ sup, const float* __restrict__ mem,
             float* __restrict__ out, int M) {
    __shared__ float  s_inv[S_SHOT * W_WAY];
    __shared__ float4 s_qw[D4];              // q for this block's way only
    __shared__ float  s_sup[S_SHOT];         // support self-sims for this way
    __shared__ float  sv[FT_THREADS * TOPK];
    __shared__ int    si[FT_THREADS * TOPK];

    int w = blockIdx.x;
    int tid = threadIdx.x, wid = tid >> 5, lane = tid & 31;
    const float4* sup4 = reinterpret_cast<const float4*>(sup);

    // inverse norms of all 25 support vectors
    for (int v = wid; v < S_SHOT * W_WAY; v += FT_THREADS / 32) {
        const float4* p = sup4 + v * D4;
        float ss = 0.f;
        #pragma unroll
        for (int j = 0; j < 5; ++j) { float4 x = p[lane + j * 32]; ss += dot4(x, x); }
        #pragma unroll
        for (int o = 16; o; o >>= 1) ss += __shfl_xor_sync(0xffffffffu, ss, o);
        if (lane == 0) s_inv[v] = 1.0f / fmaxf(sqrtf(ss), 1e-12f);
    }
    __syncthreads();

    // q for way w
    for (int d = tid; d < D4; d += FT_THREADS) {
        float4 acc = make_float4(0.f, 0.f, 0.f, 0.f);
        #pragma unroll
        for (int s = 0; s < S_SHOT; ++s) {
            float4 x = sup4[(s * W_WAY + w) * D4 + d];
            float iv = s_inv[s * W_WAY + w] * (1.0f / (float)S_SHOT);
            acc.x += x.x * iv; acc.y += x.y * iv; acc.z += x.z * iv; acc.w += x.w * iv;
        }
        s_qw[d] = acc;
    }
    __syncthreads();

    // 5 support self-sims for this way
    if (wid < S_SHOT) {
        int m = wid;
        const float4* p = sup4 + (m * W_WAY + w) * D4;
        float dpv = 0.f;
        #pragma unroll
        for (int j = 0; j < 5; ++j) dpv += dot4(s_qw[lane + j * 32], p[lane + j * 32]);
        #pragma unroll
        for (int o = 16; o; o >>= 1) dpv += __shfl_xor_sync(0xffffffffu, dpv, o);
        if (lane == 0) s_sup[m] = dpv * s_inv[m * W_WAY + w];
    }
    __syncthreads();

    // per-thread top-8 over the candidate buffer
    float av[TOPK]; int ai[TOPK];
    #pragma unroll
    for (int k = 0; k < TOPK; ++k) { av[k] = -FLT_MAX; ai[k] = 0x7fffffff; }

    for (int c = tid; c < NCAND; c += FT_THREADS) {
        float x = g_candv[w][c]; int i = g_candi[w][c];
        if (better(x, i, av[7], ai[7])) {
            #pragma unroll
            for (int t = 0; t < TOPK; ++t) {
                if (better(x, i, av[t], ai[t])) {
                    #pragma unroll
                    for (int u = TOPK - 1; u > t; --u) { av[u] = av[u-1]; ai[u] = ai[u-1]; }
                    av[t] = x; ai[t] = i;
                    break;
                }
            }
        }
    }
    // thread 0 folds in the support candidates (indices 0..4)
    if (tid == 0) {
        #pragma unroll
        for (int s = 0; s < S_SHOT; ++s) {
            float x = s_sup[s]; int i = s;
            if (better(x, i, av[7], ai[7])) {
                #pragma unroll
                for (int t = 0; t < TOPK; ++t) {
                    if (better(x, i, av[t], ai[t])) {
                        #pragma unroll
                        for (int u = TOPK - 1; u > t; --u) { av[u] = av[u-1]; ai[u] = ai[u-1]; }
                        av[t] = x; ai[t] = i;
                        break;
                    }
                }
            }
        }
    }

    #pragma unroll
    for (int k = 0; k < TOPK; ++k) { sv[tid * TOPK + k] = av[k]; si[tid * TOPK + k] = ai[k]; }
    tree_merge8<FT_THREADS>(sv, si, tid);

    // gather: out[w][d] = sum_k wt_k * row(ind_k)[d] / sum_k wt_k
    float wt[TOPK]; const float* rowp[TOPK];
    float den = 0.f;
    #pragma unroll
    for (int k = 0; k < TOPK; ++k) {
        wt[k] = sv[k];
        int m = si[k];
        rowp[k] = (m < S_SHOT) ? (sup + (m * W_WAY + w) * D_DIM)
                               : (mem + (size_t)(m - S_SHOT) * D_DIM);
        den += wt[k];
    }
    float rden = 1.0f / den;
    for (int d = tid; d < D_DIM; d += FT_THREADS) {
        float acc = 0.f;
        #pragma unroll
        for (int k = 0; k < TOPK; ++k) acc += wt[k] * rowp[k][d];
        out[w * D_DIM + d] = acc * rden;
    }
}

// ---------------------------------------------------------------------------
extern "C" void kernel_launch(void* const* d_in, const int* in_sizes, int n_in,
                              void* d_out, int out_size) {
    const float* sup = (const float*)d_in[0];   // [1,5,5,640]
    const float* mem = (const float*)d_in[1];   // [M,640]
    float* out = (float*)d_out;                 // [1,5,640]

    int M = in_sizes[1] / D_DIM;
    if (M > M_MAX) M = M_MAX;

    sim_kernel<<<SIM_BLOCKS, SIM_THREADS>>>(sup, mem, M);
    dim3 pt_grid(PT_SLICES, W_WAY);
    partial_topk<<<pt_grid, PT_THREADS>>>(M);
    final_kernel<<<W_WAY, FT_THREADS>>>(sup, mem, out, M);
}

// round 7
// speedup vs baseline: 1.7286x; 1.7286x over previous
#include <cuda_runtime.h>
#include <math.h>
#include <float.h>

// Problem constants (shapes fixed by setup_inputs)
#define D_DIM  640
#define D4     160         // D_DIM / 4
#define S_SHOT 5
#define W_WAY  5
#define TOPK   8
#define M_MAX  50000
#define NS_MAX (M_MAX + S_SHOT)

#define SIM_BLOCKS  592    // 4 blocks/SM * 148
#define SIM_THREADS 256
#define SIM_WARPS   (SIM_THREADS / 32)

#define PT_SLICES   64     // partial top-k blocks per way
#define PT_THREADS  256
#define NCAND       (PT_SLICES * TOPK)

// Static device scratch (no allocations allowed)
__device__ float g_sim[W_WAY][NS_MAX];     // sim[w][m]; slots 0..4 unused here
__device__ float g_candv[W_WAY][NCAND];
__device__ int   g_candi[W_WAY][NCAND];

__device__ __forceinline__ float dot4(float4 a, float4 b) {
    return a.x * b.x + a.y * b.y + a.z * b.z + a.w * b.w;
}

// ---------------------------------------------------------------------------
// Sorted-8 (desc) register list helpers.
// Strictly-greater compare => earlier-seen (lower index) wins on ties.
// ---------------------------------------------------------------------------
#define INS(J) do {                                        \
    _Pragma("unroll")                                      \
    for (int kk = TOPK - 1; kk > (J); --kk) {              \
        av[kk] = av[kk - 1]; ai[kk] = ai[kk - 1];          \
    }                                                      \
    av[J] = x; ai[J] = i;                                  \
} while (0)

#define FILTER_INSERT() do {                                            \
    if (x > av[7]) {                                                    \
        if (x > av[3]) {                                                \
            if (x > av[1]) { if (x > av[0]) INS(0); else INS(1); }      \
            else           { if (x > av[2]) INS(2); else INS(3); }      \
        } else {                                                        \
            if (x > av[5]) { if (x > av[4]) INS(4); else INS(5); }      \
            else           { if (x > av[6]) INS(6); else INS(7); }      \
        }                                                               \
    }                                                                   \
} while (0)

__device__ __forceinline__ bool better(float x, int i, float y, int j) {
    return (x > y) || (x == y && i < j);
}

// Shared-memory tree merge of NT sorted-8 lists (desc, index-asc ties).
template <int NT>
__device__ __forceinline__ void tree_merge8(float* sv, int* si, int tid) {
    for (int stride = NT >> 1; stride >= 1; stride >>= 1) {
        __syncthreads();
        if (tid < stride) {
            float la[TOPK], lb[TOPK], ov[TOPK];
            int   lia[TOPK], lib[TOPK], oi[TOPK];
            #pragma unroll
            for (int k = 0; k < TOPK; ++k) {
                la[k]  = sv[tid * TOPK + k];            lia[k] = si[tid * TOPK + k];
                lb[k]  = sv[(tid + stride) * TOPK + k]; lib[k] = si[(tid + stride) * TOPK + k];
            }
            int pa = 0, pb = 0;
            #pragma unroll
            for (int k = 0; k < TOPK; ++k) {
                bool takeA = (la[pa] > lb[pb]) ||
                             (la[pa] == lb[pb] && lia[pa] <= lib[pb]);
                if (takeA) { ov[k] = la[pa]; oi[k] = lia[pa]; ++pa; }
                else       { ov[k] = lb[pb]; oi[k] = lib[pb]; ++pb; }
            }
            #pragma unroll
            for (int k = 0; k < TOPK; ++k) { sv[tid * TOPK + k] = ov[k]; si[tid * TOPK + k] = oi[k]; }
        }
    }
    __syncthreads();
}

// ---------------------------------------------------------------------------
// Kernel 1: the 128 MB streaming pass (EXACT R3 version; measured ~53.7us).
// Warp handles 2 rows at a time: contiguous 512B warp loads, q reused across
// the row pair, 12 accumulators, shfl_down reduce, lane 0 writes sim.
// ---------------------------------------------------------------------------
__global__ void __launch_bounds__(SIM_THREADS, 4)
sim_kernel(const float* __restrict__ sup, const float* __restrict__ mem, int M) {
    __shared__ float  s_inv[S_SHOT * W_WAY];
    __shared__ float4 s_q[W_WAY * D4];        // 12.8 KB

    int tid = threadIdx.x, wid = tid >> 5, lane = tid & 31;
    const float4* sup4 = reinterpret_cast<const float4*>(sup);

    // prep phase 1: inverse norms of the 25 support vectors
    for (int v = wid; v < S_SHOT * W_WAY; v += SIM_WARPS) {
        const float4* p = sup4 + v * D4;
        float ss = 0.f;
        #pragma unroll
        for (int j = 0; j < 5; ++j) { float4 x = p[lane + j * 32]; ss += dot4(x, x); }
        #pragma unroll
        for (int o = 16; o; o >>= 1) ss += __shfl_xor_sync(0xffffffffu, ss, o);
        if (lane == 0) s_inv[v] = 1.0f / fmaxf(sqrtf(ss), 1e-12f);
    }
    __syncthreads();

    // prep phase 2: q[w] (includes the 1/S mean factor)
    for (int i = tid; i < W_WAY * D4; i += SIM_THREADS) {
        int w = i / D4, d = i - w * D4;
        float4 acc = make_float4(0.f, 0.f, 0.f, 0.f);
        #pragma unroll
        for (int s = 0; s < S_SHOT; ++s) {
            float4 x = sup4[(s * W_WAY + w) * D4 + d];
            float iv = s_inv[s * W_WAY + w] * (1.0f / (float)S_SHOT);
            acc.x += x.x * iv; acc.y += x.y * iv; acc.z += x.z * iv; acc.w += x.w * iv;
        }
        s_q[i] = acc;
    }
    __syncthreads();

    // mainloop: balanced contiguous partition of row-pairs across all warps
    int pairs = (M + 1) >> 1;
    int gw = blockIdx.x * SIM_WARPS + wid;
    int nw = SIM_BLOCKS * SIM_WARPS;
    int pb = (int)(((long long)gw * pairs) / nw);
    int pe = (int)(((long long)(gw + 1) * pairs) / nw);

    const float4* base = reinterpret_cast<const float4*>(mem);

    for (int p = pb; p < pe; ++p) {
        int row0 = p << 1;
        int row1 = min(row0 + 1, M - 1);     // clamp (no tail at M=50000)
        const float4* r0 = base + (size_t)row0 * D4;
        const float4* r1 = base + (size_t)row1 * D4;

        float ss0 = 0.f, ss1 = 0.f;
        float dp0[W_WAY] = {0.f, 0.f, 0.f, 0.f, 0.f};
        float dp1[W_WAY] = {0.f, 0.f, 0.f, 0.f, 0.f};

        #pragma unroll
        for (int i = 0; i < 5; ++i) {
            int idx = lane + (i << 5);
            float4 v0 = r0[idx];
            float4 v1 = r1[idx];
            ss0 += dot4(v0, v0);
            ss1 += dot4(v1, v1);
            #pragma unroll
            for (int w = 0; w < W_WAY; ++w) {
                float4 a = s_q[w * D4 + idx];
                dp0[w] += dot4(v0, a);
                dp1[w] += dot4(v1, a);
            }
        }
        #pragma unroll
        for (int o = 16; o; o >>= 1) {
            ss0 += __shfl_down_sync(0xffffffffu, ss0, o);
            ss1 += __shfl_down_sync(0xffffffffu, ss1, o);
            #pragma unroll
            for (int w = 0; w < W_WAY; ++w) {
                dp0[w] += __shfl_down_sync(0xffffffffu, dp0[w], o);
                dp1[w] += __shfl_down_sync(0xffffffffu, dp1[w], o);
            }
        }
        if (lane == 0) {
            float i0 = 1.0f / fmaxf(sqrtf(ss0), 1e-12f);
            float i1 = 1.0f / fmaxf(sqrtf(ss1), 1e-12f);
            #pragma unroll
            for (int w = 0; w < W_WAY; ++w) {
                g_sim[w][S_SHOT + row0] = dp0[w] * i0;
                if (row1 != row0) g_sim[w][S_SHOT + row1] = dp1[w] * i1;
            }
        }
    }
}

// ---------------------------------------------------------------------------
// Kernel 2: parallel partial top-k. Grid (PT_SLICES, W_WAY). Each block scans
// a contiguous slice of g_sim[w] (L2-hot), produces its top-8 candidates.
// ---------------------------------------------------------------------------
__global__ void __launch_bounds__(PT_THREADS)
partial_topk(int M) {
    __shared__ float sv[PT_THREADS * TOPK];
    __shared__ int   si[PT_THREADS * TOPK];
    int w = blockIdx.y;
    int slice = blockIdx.x;
    int tid = threadIdx.x;

    int beg = (int)(((long long)slice * M) / PT_SLICES);
    int end = (int)(((long long)(slice + 1) * M) / PT_SLICES);

    float av[TOPK]; int ai[TOPK];
    #pragma unroll
    for (int k = 0; k < TOPK; ++k) { av[k] = -FLT_MAX; ai[k] = 0x7fffffff; }

    for (int m = beg + tid; m < end; m += PT_THREADS) {
        int i = S_SHOT + m;
        float x = g_sim[w][i];
        FILTER_INSERT();
    }

    #pragma unroll
    for (int k = 0; k < TOPK; ++k) { sv[tid * TOPK + k] = av[k]; si[tid * TOPK + k] = ai[k]; }
    tree_merge8<PT_THREADS>(sv, si, tid);

    if (tid < TOPK) {
        g_candv[w][slice * TOPK + tid] = sv[tid];
        g_candi[w][slice * TOPK + tid] = si[tid];
    }
}

// ---------------------------------------------------------------------------
// Kernel 3: per-way final merge + gather. Recomputes the 5 support self-sims
// locally (tiny, L2-hot), merges the 512 candidates + support, gathers rows.
// ---------------------------------------------------------------------------
#define FT_THREADS 256

__global__ void __launch_bounds__(FT_THREADS)
final_kernel(const float* __restrict__ sup, const float* __restrict__ mem,
             float* __restrict__ out, int M) {
    __shared__ float  s_inv[S_SHOT * W_WAY];
    __shared__ float4 s_qw[D4];              // q for this block's way only
    __shared__ float  s_sup[S_SHOT];         // support self-sims for this way
    __shared__ float  sv[FT_THREADS * TOPK];
    __shared__ int    si[FT_THREADS * TOPK];

    int w = blockIdx.x;
    int tid = threadIdx.x, wid = tid >> 5, lane = tid & 31;
    const float4* sup4 = reinterpret_cast<const float4*>(sup);

    // inverse norms of all 25 support vectors
    for (int v = wid; v < S_SHOT * W_WAY; v += FT_THREADS / 32) {
        const float4* p = sup4 + v * D4;
        float ss = 0.f;
        #pragma unroll
        for (int j = 0; j < 5; ++j) { float4 x = p[lane + j * 32]; ss += dot4(x, x); }
        #pragma unroll
        for (int o = 16; o; o >>= 1) ss += __shfl_xor_sync(0xffffffffu, ss, o);
        if (lane == 0) s_inv[v] = 1.0f / fmaxf(sqrtf(ss), 1e-12f);
    }
    __syncthreads();

    // q for way w
    for (int d = tid; d < D4; d += FT_THREADS) {
        float4 acc = make_float4(0.f, 0.f, 0.f, 0.f);
        #pragma unroll
        for (int s = 0; s < S_SHOT; ++s) {
            float4 x = sup4[(s * W_WAY + w) * D4 + d];
            float iv = s_inv[s * W_WAY + w] * (1.0f / (float)S_SHOT);
            acc.x += x.x * iv; acc.y += x.y * iv; acc.z += x.z * iv; acc.w += x.w * iv;
        }
        s_qw[d] = acc;
    }
    __syncthreads();

    // 5 support self-sims for this way
    if (wid < S_SHOT) {
        int m = wid;
        const float4* p = sup4 + (m * W_WAY + w) * D4;
        float dpv = 0.f;
        #pragma unroll
        for (int j = 0; j < 5; ++j) dpv += dot4(s_qw[lane + j * 32], p[lane + j * 32]);
        #pragma unroll
        for (int o = 16; o; o >>= 1) dpv += __shfl_xor_sync(0xffffffffu, dpv, o);
        if (lane == 0) s_sup[m] = dpv * s_inv[m * W_WAY + w];
    }
    __syncthreads();

    // per-thread top-8 over the candidate buffer
    float av[TOPK]; int ai[TOPK];
    #pragma unroll
    for (int k = 0; k < TOPK; ++k) { av[k] = -FLT_MAX; ai[k] = 0x7fffffff; }

    for (int c = tid; c < NCAND; c += FT_THREADS) {
        float x = g_candv[w][c]; int i = g_candi[w][c];
        if (better(x, i, av[7], ai[7])) {
            #pragma unroll
            for (int t = 0; t < TOPK; ++t) {
                if (better(x, i, av[t], ai[t])) {
                    #pragma unroll
                    for (int u = TOPK - 1; u > t; --u) { av[u] = av[u-1]; ai[u] = ai[u-1]; }
                    av[t] = x; ai[t] = i;
                    break;
                }
            }
        }
    }
    // thread 0 folds in the support candidates (indices 0..4)
    if (tid == 0) {
        #pragma unroll
        for (int s = 0; s < S_SHOT; ++s) {
            float x = s_sup[s]; int i = s;
            if (better(x, i, av[7], ai[7])) {
                #pragma unroll
                for (int t = 0; t < TOPK; ++t) {
                    if (better(x, i, av[t], ai[t])) {
                        #pragma unroll
                        for (int u = TOPK - 1; u > t; --u) { av[u] = av[u-1]; ai[u] = ai[u-1]; }
                        av[t] = x; ai[t] = i;
                        break;
                    }
                }
            }
        }
    }

    #pragma unroll
    for (int k = 0; k < TOPK; ++k) { sv[tid * TOPK + k] = av[k]; si[tid * TOPK + k] = ai[k]; }
    tree_merge8<FT_THREADS>(sv, si, tid);

    // gather: out[w][d] = sum_k wt_k * row(ind_k)[d] / sum_k wt_k
    float wt[TOPK]; const float* rowp[TOPK];
    float den = 0.f;
    #pragma unroll
    for (int k = 0; k < TOPK; ++k) {
        wt[k] = sv[k];
        int m = si[k];
        rowp[k] = (m < S_SHOT) ? (sup + (m * W_WAY + w) * D_DIM)
                               : (mem + (size_t)(m - S_SHOT) * D_DIM);
        den += wt[k];
    }
    float rden = 1.0f / den;
    for (int d = tid; d < D_DIM; d += FT_THREADS) {
        float acc = 0.f;
        #pragma unroll
        for (int k = 0; k < TOPK; ++k) acc += wt[k] * rowp[k][d];
        out[w * D_DIM + d] = acc * rden;
    }
}

// ---------------------------------------------------------------------------
extern "C" void kernel_launch(void* const* d_in, const int* in_sizes, int n_in,
                              void* d_out, int out_size) {
    const float* sup = (const float*)d_in[0];   // [1,5,5,640]
    const float* mem = (const float*)d_in[1];   // [M,640]
    float* out = (float*)d_out;                 // [1,5,640]

    int M = in_sizes[1] / D_DIM;
    if (M > M_MAX) M = M_MAX;

    sim_kernel<<<SIM_BLOCKS, SIM_THREADS>>>(sup, mem, M);
    dim3 pt_grid(PT_SLICES, W_WAY);
    partial_topk<<<pt_grid, PT_THREADS>>>(M);
    final_kernel<<<W_WAY, FT_THREADS>>>(sup, mem, out, M);
}

// round 9
// speedup vs baseline: 2.1429x; 1.2397x over previous
#include <cuda_runtime.h>
#include <math.h>
#include <float.h>

// Problem constants (shapes fixed by setup_inputs)
#define D_DIM  640
#define D4     160         // D_DIM / 4
#define S_SHOT 5
#define W_WAY  5
#define TOPK   8
#define M_MAX  50000
#define NS_MAX (M_MAX + S_SHOT)

#define SIM_BLOCKS  444    // 3 blocks/SM * 148 -> exactly one wave at (256,3)
#define SIM_THREADS 256
#define SIM_WARPS   (SIM_THREADS / 32)

#define PT_SLICES   64     // partial top-k blocks per way
#define PT_THREADS  256
#define NCAND       (PT_SLICES * TOPK)

// Static device scratch (no allocations allowed)
__device__ float g_sim[W_WAY][NS_MAX];     // sim[w][m]; slots 0..4 unused here
__device__ float g_candv[W_WAY][NCAND];
__device__ int   g_candi[W_WAY][NCAND];

__device__ __forceinline__ float dot4(float4 a, float4 b) {
    return a.x * b.x + a.y * b.y + a.z * b.z + a.w * b.w;
}

// ---------------------------------------------------------------------------
// Sorted-8 (desc) register list helpers.
// Strictly-greater compare => earlier-seen (lower index) wins on ties.
// ---------------------------------------------------------------------------
#define INS(J) do {                                        \
    _Pragma("unroll")                                      \
    for (int kk = TOPK - 1; kk > (J); --kk) {              \
        av[kk] = av[kk - 1]; ai[kk] = ai[kk - 1];          \
    }                                                      \
    av[J] = x; ai[J] = i;                                  \
} while (0)

#define FILTER_INSERT() do {                                            \
    if (x > av[7]) {                                                    \
        if (x > av[3]) {                                                \
            if (x > av[1]) { if (x > av[0]) INS(0); else INS(1); }      \
            else           { if (x > av[2]) INS(2); else INS(3); }      \
        } else {                                                        \
            if (x > av[5]) { if (x > av[4]) INS(4); else INS(5); }      \
            else           { if (x > av[6]) INS(6); else INS(7); }      \
        }                                                               \
    }                                                                   \
} while (0)

__device__ __forceinline__ bool better(float x, int i, float y, int j) {
    return (x > y) || (x == y && i < j);
}

// Shared-memory tree merge of NT sorted-8 lists (desc, index-asc ties).
template <int NT>
__device__ __forceinline__ void tree_merge8(float* sv, int* si, int tid) {
    for (int stride = NT >> 1; stride >= 1; stride >>= 1) {
        __syncthreads();
        if (tid < stride) {
            float la[TOPK], lb[TOPK], ov[TOPK];
            int   lia[TOPK], lib[TOPK], oi[TOPK];
            #pragma unroll
            for (int k = 0; k < TOPK; ++k) {
                la[k]  = sv[tid * TOPK + k];            lia[k] = si[tid * TOPK + k];
                lb[k]  = sv[(tid + stride) * TOPK + k]; lib[k] = si[(tid + stride) * TOPK + k];
            }
            int pa = 0, pb = 0;
            #pragma unroll
            for (int k = 0; k < TOPK; ++k) {
                bool takeA = (la[pa] > lb[pb]) ||
                             (la[pa] == lb[pb] && lia[pa] <= lib[pb]);
                if (takeA) { ov[k] = la[pa]; oi[k] = lia[pa]; ++pa; }
                else       { ov[k] = lb[pb]; oi[k] = lib[pb]; ++pb; }
            }
            #pragma unroll
            for (int k = 0; k < TOPK; ++k) { sv[tid * TOPK + k] = ov[k]; si[tid * TOPK + k] = oi[k]; }
        }
    }
    __syncthreads();
}

// ---------------------------------------------------------------------------
// Kernel 1: the 128 MB streaming pass. 2 rows per warp, contiguous 512B warp
// loads, q reused across the pair, 12 accumulators, shfl_down reduce.
// __launch_bounds__(256,3): 85-reg budget -> no spills (R7's (256,4)=64 regs
// spilled ~8 regs/pair -> ~90MB of extra DRAM traffic, measured 221MB vs 130).
// ---------------------------------------------------------------------------
__global__ void __launch_bounds__(SIM_THREADS, 3)
sim_kernel(const float* __restrict__ sup, const float* __restrict__ mem, int M) {
    __shared__ float  s_inv[S_SHOT * W_WAY];
    __shared__ float4 s_q[W_WAY * D4];        // 12.8 KB

    int tid = threadIdx.x, wid = tid >> 5, lane = tid & 31;
    const float4* sup4 = reinterpret_cast<const float4*>(sup);

    // prep phase 1: inverse norms of the 25 support vectors
    for (int v = wid; v < S_SHOT * W_WAY; v += SIM_WARPS) {
        const float4* p = sup4 + v * D4;
        float ss = 0.f;
        #pragma unroll
        for (int j = 0; j < 5; ++j) { float4 x = p[lane + j * 32]; ss += dot4(x, x); }
        #pragma unroll
        for (int o = 16; o; o >>= 1) ss += __shfl_xor_sync(0xffffffffu, ss, o);
        if (lane == 0) s_inv[v] = 1.0f / fmaxf(sqrtf(ss), 1e-12f);
    }
    __syncthreads();

    // prep phase 2: q[w] (includes the 1/S mean factor)
    for (int i = tid; i < W_WAY * D4; i += SIM_THREADS) {
        int w = i / D4, d = i - w * D4;
        float4 acc = make_float4(0.f, 0.f, 0.f, 0.f);
        #pragma unroll
        for (int s = 0; s < S_SHOT; ++s) {
            float4 x = sup4[(s * W_WAY + w) * D4 + d];
            float iv = s_inv[s * W_WAY + w] * (1.0f / (float)S_SHOT);
            acc.x += x.x * iv; acc.y += x.y * iv; acc.z += x.z * iv; acc.w += x.w * iv;
        }
        s_q[i] = acc;
    }
    __syncthreads();

    // mainloop: balanced contiguous partition of row-pairs across all warps
    int pairs = (M + 1) >> 1;
    int gw = blockIdx.x * SIM_WARPS + wid;
    int nw = SIM_BLOCKS * SIM_WARPS;
    int pb = (int)(((long long)gw * pairs) / nw);
    int pe = (int)(((long long)(gw + 1) * pairs) / nw);

    const float4* base = reinterpret_cast<const float4*>(mem);

    for (int p = pb; p < pe; ++p) {
        int row0 = p << 1;
        int row1 = min(row0 + 1, M - 1);     // clamp (no tail at M=50000)
        const float4* r0 = base + (size_t)row0 * D4;
        const float4* r1 = base + (size_t)row1 * D4;

        float ss0 = 0.f, ss1 = 0.f;
        float dp0[W_WAY] = {0.f, 0.f, 0.f, 0.f, 0.f};
        float dp1[W_WAY] = {0.f, 0.f, 0.f, 0.f, 0.f};

        #pragma unroll
        for (int i = 0; i < 5; ++i) {
            int idx = lane + (i << 5);
            float4 v0 = r0[idx];
            float4 v1 = r1[idx];
            ss0 += dot4(v0, v0);
            ss1 += dot4(v1, v1);
            #pragma unroll
            for (int w = 0; w < W_WAY; ++w) {
                float4 a = s_q[w * D4 + idx];
                dp0[w] += dot4(v0, a);
                dp1[w] += dot4(v1, a);
            }
        }
        #pragma unroll
        for (int o = 16; o; o >>= 1) {
            ss0 += __shfl_down_sync(0xffffffffu, ss0, o);
            ss1 += __shfl_down_sync(0xffffffffu, ss1, o);
            #pragma unroll
            for (int w = 0; w < W_WAY; ++w) {
                dp0[w] += __shfl_down_sync(0xffffffffu, dp0[w], o);
                dp1[w] += __shfl_down_sync(0xffffffffu, dp1[w], o);
            }
        }
        if (lane == 0) {
            float i0 = 1.0f / fmaxf(sqrtf(ss0), 1e-12f);
            float i1 = 1.0f / fmaxf(sqrtf(ss1), 1e-12f);
            #pragma unroll
            for (int w = 0; w < W_WAY; ++w) {
                g_sim[w][S_SHOT + row0] = dp0[w] * i0;
                if (row1 != row0) g_sim[w][S_SHOT + row1] = dp1[w] * i1;
            }
        }
    }
}

// ---------------------------------------------------------------------------
// Kernel 2: parallel partial top-k. Grid (PT_SLICES, W_WAY). Each block scans
// a contiguous slice of g_sim[w] (L2-hot), produces its top-8 candidates.
// ---------------------------------------------------------------------------
__global__ void __launch_bounds__(PT_THREADS)
partial_topk(int M) {
    __shared__ float sv[PT_THREADS * TOPK];
    __shared__ int   si[PT_THREADS * TOPK];
    int w = blockIdx.y;
    int slice = blockIdx.x;
    int tid = threadIdx.x;

    int beg = (int)(((long long)slice * M) / PT_SLICES);
    int end = (int)(((long long)(slice + 1) * M) / PT_SLICES);

    float av[TOPK]; int ai[TOPK];
    #pragma unroll
    for (int k = 0; k < TOPK; ++k) { av[k] = -FLT_MAX; ai[k] = 0x7fffffff; }

    for (int m = beg + tid; m < end; m += PT_THREADS) {
        int i = S_SHOT + m;
        float x = g_sim[w][i];
        FILTER_INSERT();
    }

    #pragma unroll
    for (int k = 0; k < TOPK; ++k) { sv[tid * TOPK + k] = av[k]; si[tid * TOPK + k] = ai[k]; }
    tree_merge8<PT_THREADS>(sv, si, tid);

    if (tid < TOPK) {
        g_candv[w][slice * TOPK + tid] = sv[tid];
        g_candi[w][slice * TOPK + tid] = si[tid];
    }
}

// ---------------------------------------------------------------------------
// Kernel 3: per-way final merge + gather. Recomputes the 5 support self-sims
// locally (tiny, L2-hot), merges the 512 candidates + support, gathers rows.
// ---------------------------------------------------------------------------
#define FT_THREADS 256

__global__ void __launch_bounds__(FT_THREADS)
final_kernel(const float* __restrict__ sup, const float* __restrict__ mem,
             float* __restrict__ out, int M) {
    __shared__ float  s_inv[S_SHOT * W_WAY];
    __shared__ float4 s_qw[D4];              // q for this block's way only
    __shared__ float  s_sup[S_SHOT];         // support self-sims for this way
    __shared__ float  sv[FT_THREADS * TOPK];
    __shared__ int    si[FT_THREADS * TOPK];

    int w = blockIdx.x;
    int tid = threadIdx.x, wid = tid >> 5, lane = tid & 31;
    const float4* sup4 = reinterpret_cast<const float4*>(sup);

    // inverse norms of all 25 support vectors
    for (int v = wid; v < S_SHOT * W_WAY; v += FT_THREADS / 32) {
        const float4* p = sup4 + v * D4;
        float ss = 0.f;
        #pragma unroll
        for (int j = 0; j < 5; ++j) { float4 x = p[lane + j * 32]; ss += dot4(x, x); }
        #pragma unroll
        for (int o = 16; o; o >>= 1) ss += __shfl_xor_sync(0xffffffffu, ss, o);
        if (lane == 0) s_inv[v] = 1.0f / fmaxf(sqrtf(ss), 1e-12f);
    }
    __syncthreads();

    // q for way w
    for (int d = tid; d < D4; d += FT_THREADS) {
        float4 acc = make_float4(0.f, 0.f, 0.f, 0.f);
        #pragma unroll
        for (int s = 0; s < S_SHOT; ++s) {
            float4 x = sup4[(s * W_WAY + w) * D4 + d];
            float iv = s_inv[s * W_WAY + w] * (1.0f / (float)S_SHOT);
            acc.x += x.x * iv; acc.y += x.y * iv; acc.z += x.z * iv; acc.w += x.w * iv;
        }
        s_qw[d] = acc;
    }
    __syncthreads();

    // 5 support self-sims for this way
    if (wid < S_SHOT) {
        int m = wid;
        const float4* p = sup4 + (m * W_WAY + w) * D4;
        float dpv = 0.f;
        #pragma unroll
        for (int j = 0; j < 5; ++j) dpv += dot4(s_qw[lane + j * 32], p[lane + j * 32]);
        #pragma unroll
        for (int o = 16; o; o >>= 1) dpv += __shfl_xor_sync(0xffffffffu, dpv, o);
        if (lane == 0) s_sup[m] = dpv * s_inv[m * W_WAY + w];
    }
    __syncthreads();

    // per-thread top-8 over the candidate buffer
    float av[TOPK]; int ai[TOPK];
    #pragma unroll
    for (int k = 0; k < TOPK; ++k) { av[k] = -FLT_MAX; ai[k] = 0x7fffffff; }

    for (int c = tid; c < NCAND; c += FT_THREADS) {
        float x = g_candv[w][c]; int i = g_candi[w][c];
        if (better(x, i, av[7], ai[7])) {
            #pragma unroll
            for (int t = 0; t < TOPK; ++t) {
                if (better(x, i, av[t], ai[t])) {
                    #pragma unroll
                    for (int u = TOPK - 1; u > t; --u) { av[u] = av[u-1]; ai[u] = ai[u-1]; }
                    av[t] = x; ai[t] = i;
                    break;
                }
            }
        }
    }
    // thread 0 folds in the support candidates (indices 0..4)
    if (tid == 0) {
        #pragma unroll
        for (int s = 0; s < S_SHOT; ++s) {
            float x = s_sup[s]; int i = s;
            if (better(x, i, av[7], ai[7])) {
                #pragma unroll
                for (int t = 0; t < TOPK; ++t) {
                    if (better(x, i, av[t], ai[t])) {
                        #pragma unroll
                        for (int u = TOPK - 1; u > t; --u) { av[u] = av[u-1]; ai[u] = ai[u-1]; }
                        av[t] = x; ai[t] = i;
                        break;
                    }
                }
            }
        }
    }

    #pragma unroll
    for (int k = 0; k < TOPK; ++k) { sv[tid * TOPK + k] = av[k]; si[tid * TOPK + k] = ai[k]; }
    tree_merge8<FT_THREADS>(sv, si, tid);

    // gather: out[w][d] = sum_k wt_k * row(ind_k)[d] / sum_k wt_k
    float wt[TOPK]; const float* rowp[TOPK];
    float den = 0.f;
    #pragma unroll
    for (int k = 0; k < TOPK; ++k) {
        wt[k] = sv[k];
        int m = si[k];
        rowp[k] = (m < S_SHOT) ? (sup + (m * W_WAY + w) * D_DIM)
                               : (mem + (size_t)(m - S_SHOT) * D_DIM);
        den += wt[k];
    }
    float rden = 1.0f / den;
    for (int d = tid; d < D_DIM; d += FT_THREADS) {
        float acc = 0.f;
        #pragma unroll
        for (int k = 0; k < TOPK; ++k) acc += wt[k] * rowp[k][d];
        out[w * D_DIM + d] = acc * rden;
    }
}

// ---------------------------------------------------------------------------
extern "C" void kernel_launch(void* const* d_in, const int* in_sizes, int n_in,
                              void* d_out, int out_size) {
    const float* sup = (const float*)d_in[0];   // [1,5,5,640]
    const float* mem = (const float*)d_in[1];   // [M,640]
    float* out = (float*)d_out;                 // [1,5,640]

    int M = in_sizes[1] / D_DIM;
    if (M > M_MAX) M = M_MAX;

    sim_kernel<<<SIM_BLOCKS, SIM_THREADS>>>(sup, mem, M);
    dim3 pt_grid(PT_SLICES, W_WAY);
    partial_topk<<<pt_grid, PT_THREADS>>>(M);
    final_kernel<<<W_WAY, FT_THREADS>>>(sup, mem, out, M);
}